// round 14
// baseline (speedup 1.0000x reference)
#include <cuda_runtime.h>
#include <cuda_bf16.h>
#include <math.h>
#include <stdint.h>

#define Bx 4
#define Nx 8192
#define Cx 64
#define Dx 128
#define Sx 2048
#define Kx 32
#define HALF 4096

// Scratch buffers
__device__ unsigned long long g_part[Bx * Sx * 2 * Kx];   // 4 MB
__device__ int g_knn[Bx * Sx * Kx];
__device__ float g_z1f[Bx * Nx * Dx];                     // 16 MB: feat @ W1_feat

// ---------------------------------------------------------------------------
// Math helpers
// ---------------------------------------------------------------------------
__device__ __forceinline__ float gelu_f(float x) {
    float z = fabsf(x) * 0.70710678118654752440f;
    float den = fmaf(0.3275911f, z, 1.0f);
    float t;
    asm("rcp.approx.f32 %0, %1;" : "=f"(t) : "f"(den));
    float poly = t * fmaf(t, fmaf(t, fmaf(t, fmaf(t, 1.061405429f, -1.453152027f),
                                          1.421413741f), -0.284496736f), 0.254829592f);
    float ex = __expf(-z * z);
    float e = fmaf(-poly, ex, 1.0f);
    float s = copysignf(e, x);
    return 0.5f * x * (1.0f + s);
}

__device__ __forceinline__ int sample_idx(int s) {
    float q = __fdiv_rn((float)s, 2047.0f);
    return __float2int_rn(__fmul_rn(8191.0f, q));
}

__device__ __forceinline__ unsigned ordf(float f) {
    unsigned u = __float_as_uint(f);
    return u ^ ((u >> 31) ? 0xffffffffu : 0x80000000u);
}

// bf16 hi/lo split of two floats -> packed hi-word and lo-word (x1 upper half)
__device__ __forceinline__ void split_pack2(float x0, float x1,
                                            uint32_t& hw, uint32_t& lw) {
    __nv_bfloat16 h0 = __float2bfloat16_rn(x0);
    __nv_bfloat16 h1 = __float2bfloat16_rn(x1);
    __nv_bfloat16 l0 = __float2bfloat16_rn(x0 - __bfloat162float(h0));
    __nv_bfloat16 l1 = __float2bfloat16_rn(x1 - __bfloat162float(h1));
    hw = ((uint32_t)__bfloat16_as_ushort(h1) << 16) | __bfloat16_as_ushort(h0);
    lw = ((uint32_t)__bfloat16_as_ushort(l1) << 16) | __bfloat16_as_ushort(l0);
}

// m16n8k16 bf16 mma, acc in-place
__device__ __forceinline__ void mma_bf16(float* c, const uint32_t* a,
                                         const uint32_t* b) {
    asm volatile(
        "mma.sync.aligned.m16n8k16.row.col.f32.bf16.bf16.f32 "
        "{%0,%1,%2,%3}, {%4,%5,%6,%7}, {%8,%9}, {%0,%1,%2,%3};"
        : "+f"(c[0]), "+f"(c[1]), "+f"(c[2]), "+f"(c[3])
        : "r"(a[0]), "r"(a[1]), "r"(a[2]), "r"(a[3]), "r"(b[0]), "r"(b[1]));
}

__device__ __forceinline__ void recompute_max(float held, int heldIdx,
                                              float& hmax, int& maxlane) {
    unsigned hk = ordf(held);
    unsigned mk = __reduce_max_sync(0xffffffffu, hk);
    unsigned mm = __ballot_sync(0xffffffffu, hk == mk);
    if (__popc(mm) > 1) {
        unsigned cand = (hk == mk) ? (unsigned)heldIdx : 0u;
        unsigned mi = __reduce_max_sync(0xffffffffu, cand);
        mm = __ballot_sync(0xffffffffu, (hk == mk) && ((unsigned)heldIdx == mi));
    }
    maxlane = __ffs(mm) - 1;
    hmax = __shfl_sync(0xffffffffu, held, maxlane);
}

// ---------------------------------------------------------------------------
// Kernel 1: partial kNN (unchanged, 136 us measured)
// ---------------------------------------------------------------------------
__global__ __launch_bounds__(512, 2) void knn_part_kernel(
    const float* __restrict__ coords) {
    extern __shared__ float4 sh[];
    int blk = blockIdx.x;
    int half = blk & 1;
    int qg = blk >> 1;
    int b = qg >> 7;
    int warp = threadIdx.x >> 5;
    int s = ((qg & 127) << 4) + warp;
    int lane = threadIdx.x & 31;
    int base = half * HALF;

    for (int i = threadIdx.x; i < HALF; i += 512) {
        const float* c = coords + 3 * ((size_t)b * Nx + base + i);
        float x = c[0], y = c[1], z = c[2];
        sh[i] = make_float4(x, y, z, fmaf(z, z, fmaf(y, y, x * x)));
    }
    __syncthreads();

    float sx, sy, sz, s2;
    {
        const float* c = coords + 3 * ((size_t)b * Nx + sample_idx(s));
        sx = c[0]; sy = c[1]; sz = c[2];
        s2 = fmaf(sz, sz, fmaf(sy, sy, sx * sx));
    }

    float held;
    int heldIdx = base + lane;
    {
        float4 p = sh[lane];
        held = fmaf(-2.0f, fmaf(sx, p.x, fmaf(sy, p.y, sz * p.z)), s2 + p.w);
    }
    float hmax;
    int maxlane;
    recompute_max(held, heldIdx, hmax, maxlane);

    for (int n0 = Kx; n0 < HALF; n0 += 32) {
        float4 p = sh[n0 + lane];
        float d = fmaf(-2.0f, fmaf(sx, p.x, fmaf(sy, p.y, sz * p.z)), s2 + p.w);
        unsigned qm = __ballot_sync(0xffffffffu, d < hmax);
        while (qm) {
            int src = __ffs(qm) - 1;
            qm &= qm - 1;
            float v = __shfl_sync(0xffffffffu, d, src);
            if (v < hmax) {
                if (lane == maxlane) { held = v; heldIdx = base + n0 + src; }
                recompute_max(held, heldIdx, hmax, maxlane);
            }
        }
    }

    unsigned hk = ordf(held);
    g_part[((size_t)(b * Sx + s) * 2 + half) * Kx + lane] =
        ((unsigned long long)hk << 32) | (unsigned)heldIdx;
}

// ---------------------------------------------------------------------------
// Kernel 2: merge partial top-32 sets; writes sampled output (unchanged)
// ---------------------------------------------------------------------------
__global__ __launch_bounds__(512, 2) void knn_merge_kernel(
    const float* __restrict__ coords, float* __restrict__ out_sampled) {
    int q = blockIdx.x * 16 + (threadIdx.x >> 5);
    int lane = threadIdx.x & 31;

    const unsigned long long* part = g_part + (size_t)q * 2 * Kx;
    unsigned long long a = part[lane];
    unsigned long long bb = part[32 + lane];

#pragma unroll
    for (int k = 2; k <= 64; k <<= 1) {
#pragma unroll
        for (int j = k >> 1; j > 0; j >>= 1) {
            if (j >= 32) {
                unsigned long long lo = a < bb ? a : bb;
                unsigned long long hi = a < bb ? bb : a;
                a = lo; bb = hi;
            } else {
                unsigned long long pa = __shfl_xor_sync(0xffffffffu, a, j);
                unsigned long long pb = __shfl_xor_sync(0xffffffffu, bb, j);
                bool lower = ((lane & j) == 0);
                bool upA = ((lane & k) == 0) || (k == 64);
                bool upB = (((lane + 32) & k) == 0) || (k == 64);
                bool keepMinA = (lower == upA);
                bool keepMinB = (lower == upB);
                a  = keepMinA ? (a  < pa ? a  : pa) : (a  > pa ? a  : pa);
                bb = keepMinB ? (bb < pb ? bb : pb) : (bb > pb ? bb : pb);
            }
        }
    }
    g_knn[(size_t)q * Kx + lane] = (int)(a & 0xffffffffu);

    int t = blockIdx.x * 512 + threadIdx.x;
    if (t < Bx * Sx * 3) {
        int idx = t / 3, comp = t - idx * 3;
        int b2 = idx >> 11, s2i = idx & 2047;
        out_sampled[t] = coords[3 * ((size_t)b2 * Nx + sample_idx(s2i)) + comp];
    }
}

// ---------------------------------------------------------------------------
// Kernel 3: z1f precompute — per-point feature GEMM (unchanged)
// ---------------------------------------------------------------------------
#define ZSTR 136
#define SMEM_Z1F (128 * ZSTR * 4)

__global__ __launch_bounds__(256, 1) void z1f_kernel(
    const float* __restrict__ features, const float* __restrict__ W1) {
    extern __shared__ uint32_t smu[];
    uint32_t* Ah = smu;
    uint32_t* Al = smu + 32 * ZSTR;
    uint32_t* Wh = smu + 64 * ZSTR;
    uint32_t* Wl = smu + 96 * ZSTR;

    int tid = threadIdx.x;
    int wm = tid >> 5, lane = tid & 31;
    int g = lane >> 2, t4 = lane & 3;
    int j0 = wm * 16;

    for (int i = tid; i < 32 * 128; i += 256) {
        int kw = i >> 7, d = i & 127;
        float w0 = W1[(3 + 2 * kw) * Dx + d];
        float w1 = W1[(3 + 2 * kw + 1) * Dx + d];
        uint32_t hw, lw;
        split_pack2(w0, w1, hw, lw);
        Wh[kw * ZSTR + d] = hw;
        Wl[kw * ZSTR + d] = lw;
    }
    {
        int j = tid & 127, hf = tid >> 7;
        int p = blockIdx.x * 128 + j;
        const float4* f4 = (const float4*)(features + (size_t)p * Cx) + hf * 8;
#pragma unroll
        for (int q = 0; q < 8; q++) {
            float4 v = f4[q];
            int kw = hf * 16 + 2 * q;
            uint32_t hw, lw;
            split_pack2(v.x, v.y, hw, lw);
            Ah[kw * ZSTR + j] = hw;
            Al[kw * ZSTR + j] = lw;
            split_pack2(v.z, v.w, hw, lw);
            Ah[(kw + 1) * ZSTR + j] = hw;
            Al[(kw + 1) * ZSTR + j] = lw;
        }
    }
    __syncthreads();

    float acc[64];
#pragma unroll
    for (int i = 0; i < 64; i++) acc[i] = 0.0f;
#pragma unroll
    for (int k = 0; k < 4; k++) {
        int kw0 = 8 * k;
        uint32_t ah[4], al[4];
        ah[0] = Ah[(kw0 + t4) * ZSTR + j0 + g];
        ah[1] = Ah[(kw0 + t4) * ZSTR + j0 + 8 + g];
        ah[2] = Ah[(kw0 + t4 + 4) * ZSTR + j0 + g];
        ah[3] = Ah[(kw0 + t4 + 4) * ZSTR + j0 + 8 + g];
        al[0] = Al[(kw0 + t4) * ZSTR + j0 + g];
        al[1] = Al[(kw0 + t4) * ZSTR + j0 + 8 + g];
        al[2] = Al[(kw0 + t4 + 4) * ZSTR + j0 + g];
        al[3] = Al[(kw0 + t4 + 4) * ZSTR + j0 + 8 + g];
#pragma unroll
        for (int n = 0; n < 16; n++) {
            int n0 = 8 * n;
            uint32_t bh[2], bl[2];
            bh[0] = Wh[(kw0 + t4) * ZSTR + n0 + g];
            bh[1] = Wh[(kw0 + t4 + 4) * ZSTR + n0 + g];
            bl[0] = Wl[(kw0 + t4) * ZSTR + n0 + g];
            bl[1] = Wl[(kw0 + t4 + 4) * ZSTR + n0 + g];
            mma_bf16(acc + 4 * n, ah, bh);
            mma_bf16(acc + 4 * n, ah, bl);
            mma_bf16(acc + 4 * n, al, bh);
        }
    }

    float* zr0 = g_z1f + ((size_t)blockIdx.x * 128 + j0 + g) * Dx;
    float* zr1 = g_z1f + ((size_t)blockIdx.x * 128 + j0 + 8 + g) * Dx;
#pragma unroll
    for (int n = 0; n < 16; n++) {
        int c0 = 8 * n + 2 * t4;
        *(float2*)(zr0 + c0) = make_float2(acc[4 * n + 0], acc[4 * n + 1]);
        *(float2*)(zr1 + c0) = make_float2(acc[4 * n + 2], acc[4 * n + 3]);
    }
}

// ---------------------------------------------------------------------------
// Kernel 4: MLP, factorized layer 1, N-SPLIT warps: 512 thr = 16 warps;
// warp (mw, nh): rows mw*16..+15, cols nh*64..+63 (8 n-tiles), acc[32].
// ---------------------------------------------------------------------------
#define STRW 136
#define STRF 132
#define OFF_AH   0
#define OFF_AL   (64 * STRW)
#define OFF_RH   17408
#define OFF_RL   (OFF_RH + 8 * STRW)
#define OFF_W1RH (OFF_RL + 8 * STRW)
#define OFF_W1RL (OFF_W1RH + 8 * STRW)
#define OFF_W2H  (OFF_W1RL + 8 * STRW)
#define OFF_W2L  (OFF_W2H + 64 * STRW)
#define OFF_B1   (OFF_W2L + 64 * STRW)
#define OFF_B2   (OFF_B1 + 128)
#define OFF_PL   (OFF_B2 + 128)
#define SMEM_MLP ((OFF_PL + 8 * 128 * 2) * 4)   /* 165888 bytes */
#define NTILES (Bx * Sx / 4)

__global__ __launch_bounds__(512, 1) void mlp_tc_kernel(
    const float* __restrict__ coords,
    const float* __restrict__ W1, const float* __restrict__ b1,
    const float* __restrict__ W2, const float* __restrict__ b2,
    float* __restrict__ out_pooled) {
    extern __shared__ uint32_t smu[];
    uint32_t* Ah   = smu + OFF_AH;
    uint32_t* Al   = smu + OFF_AL;
    float*    zs   = (float*)smu;        // z1f staging unions Ah/Al
    uint32_t* RH   = smu + OFF_RH;
    uint32_t* RL   = smu + OFF_RL;
    uint32_t* W1rh = smu + OFF_W1RH;
    uint32_t* W1rl = smu + OFF_W1RL;
    uint32_t* W2h  = smu + OFF_W2H;
    uint32_t* W2l  = smu + OFF_W2L;
    float* b1s = (float*)(smu + OFF_B1);
    float* b2s = (float*)(smu + OFF_B2);
    float* pool = (float*)(smu + OFF_PL);

    int tid = threadIdx.x;
    int wid = tid >> 5, lane = tid & 31;
    int mw = wid & 7;            // m-warp: rows
    int nh = wid >> 3;           // n-half: cols nh*64..+63
    int g = lane >> 2, t4 = lane & 3;
    int j0 = mw * 16;

    // Stage W1_rel (kw0-1 real, kw2-7 zero) and W2, pre-split packed
    for (int i = tid; i < 2 * 128; i += 512) {
        int kw = i >> 7, d = i & 127;
        float w0 = W1[(2 * kw) * Dx + d];
        float w1 = (2 * kw + 1 < 3) ? W1[(2 * kw + 1) * Dx + d] : 0.0f;
        uint32_t hw, lw;
        split_pack2(w0, w1, hw, lw);
        W1rh[kw * STRW + d] = hw;
        W1rl[kw * STRW + d] = lw;
    }
    for (int i = tid; i < 6 * 128; i += 512) {
        int kw = 2 + (i >> 7), d = i & 127;
        W1rh[kw * STRW + d] = 0u;
        W1rl[kw * STRW + d] = 0u;
        RH[kw * STRW + d] = 0u;
        RL[kw * STRW + d] = 0u;
    }
    for (int i = tid; i < 64 * 128; i += 512) {
        int kw = i >> 7, d = i & 127;
        float w0 = W2[(2 * kw) * Dx + d];
        float w1 = W2[(2 * kw + 1) * Dx + d];
        uint32_t hw, lw;
        split_pack2(w0, w1, hw, lw);
        W2h[kw * STRW + d] = hw;
        W2l[kw * STRW + d] = lw;
    }
    if (tid < 128) { b1s[tid] = b1[tid]; b2s[tid] = b2[tid]; }
    __syncthreads();

    for (int tile = blockIdx.x; tile < NTILES; tile += gridDim.x) {
        // ---- Gather: z1f row copy (4 thr/row) + rel coords ----
        {
            int j = tid >> 2, seg = tid & 3;
            int group = tile * 4 + (j >> 5);
            int b = group >> 11, s = group & 2047;
            int ni = g_knn[(size_t)group * Kx + (j & 31)];
            const float4* zsrc =
                (const float4*)(g_z1f + ((size_t)(b * Nx + ni)) * Dx) + seg * 8;
            float* zdst = zs + j * STRF + seg * 32;
#pragma unroll
            for (int q = 0; q < 8; q++)
                *(float4*)(zdst + 4 * q) = zsrc[q];
            if (seg == 0) {
                const float* sc = coords + 3 * ((size_t)b * Nx + sample_idx(s));
                const float* pc = coords + 3 * ((size_t)b * Nx + ni);
                uint32_t hw, lw;
                split_pack2(pc[0] - sc[0], pc[1] - sc[1], hw, lw);
                RH[0 * STRW + j] = hw;
                RL[0 * STRW + j] = lw;
                split_pack2(pc[2] - sc[2], 0.0f, hw, lw);
                RH[1 * STRW + j] = hw;
                RL[1 * STRW + j] = lw;
            }
        }
        __syncthreads();

        float acc[32];

        // ---- Layer 1 lite: acc = z1f + rel @ W1r (one k16 iter, n-slice) ----
#pragma unroll
        for (int nl = 0; nl < 8; nl++) {
            int c0 = 8 * (nh * 8 + nl) + 2 * t4;
            float2 v0 = *(float2*)(zs + (j0 + g) * STRF + c0);
            float2 v1 = *(float2*)(zs + (j0 + 8 + g) * STRF + c0);
            acc[4 * nl + 0] = v0.x;
            acc[4 * nl + 1] = v0.y;
            acc[4 * nl + 2] = v1.x;
            acc[4 * nl + 3] = v1.y;
        }
        {
            uint32_t ah[4], al[4];
            ah[0] = RH[t4 * STRW + j0 + g];
            ah[1] = RH[t4 * STRW + j0 + 8 + g];
            ah[2] = RH[(t4 + 4) * STRW + j0 + g];
            ah[3] = RH[(t4 + 4) * STRW + j0 + 8 + g];
            al[0] = RL[t4 * STRW + j0 + g];
            al[1] = RL[t4 * STRW + j0 + 8 + g];
            al[2] = RL[(t4 + 4) * STRW + j0 + g];
            al[3] = RL[(t4 + 4) * STRW + j0 + 8 + g];
#pragma unroll
            for (int nl = 0; nl < 8; nl++) {
                int n0 = 8 * (nh * 8 + nl);
                uint32_t bh[2], bl[2];
                bh[0] = W1rh[t4 * STRW + n0 + g];
                bh[1] = W1rh[(t4 + 4) * STRW + n0 + g];
                bl[0] = W1rl[t4 * STRW + n0 + g];
                bl[1] = W1rl[(t4 + 4) * STRW + n0 + g];
                mma_bf16(acc + 4 * nl, ah, bh);
                mma_bf16(acc + 4 * nl, ah, bl);
                mma_bf16(acc + 4 * nl, al, bh);
            }
        }
        __syncthreads();   // zs reads done before H overwrites union region

        // ---- Epilogue 1: H = gelu(z + b1) -> Ah/Al (warp's kw slice) ----
#pragma unroll
        for (int nl = 0; nl < 8; nl++) {
            int n = nh * 8 + nl;
            int c0 = 8 * n + 2 * t4;
            int kw = 4 * n + t4;
            float bv0 = b1s[c0], bv1 = b1s[c0 + 1];
            uint32_t hw, lw;
            split_pack2(gelu_f(acc[4 * nl + 0] + bv0),
                        gelu_f(acc[4 * nl + 1] + bv1), hw, lw);
            Ah[kw * STRW + j0 + g] = hw;
            Al[kw * STRW + j0 + g] = lw;
            split_pack2(gelu_f(acc[4 * nl + 2] + bv0),
                        gelu_f(acc[4 * nl + 3] + bv1), hw, lw);
            Ah[kw * STRW + j0 + 8 + g] = hw;
            Al[kw * STRW + j0 + 8 + g] = lw;
        }
        __syncthreads();

        // ---- Layer 2: Z2 = H @ W2, K=128 (8 k16 iters, n-slice) ----
#pragma unroll
        for (int i = 0; i < 32; i++) acc[i] = 0.0f;
#pragma unroll
        for (int k = 0; k < 8; k++) {
            int kw0 = 8 * k;
            uint32_t ah[4], al[4];
            ah[0] = Ah[(kw0 + t4) * STRW + j0 + g];
            ah[1] = Ah[(kw0 + t4) * STRW + j0 + 8 + g];
            ah[2] = Ah[(kw0 + t4 + 4) * STRW + j0 + g];
            ah[3] = Ah[(kw0 + t4 + 4) * STRW + j0 + 8 + g];
            al[0] = Al[(kw0 + t4) * STRW + j0 + g];
            al[1] = Al[(kw0 + t4) * STRW + j0 + 8 + g];
            al[2] = Al[(kw0 + t4 + 4) * STRW + j0 + g];
            al[3] = Al[(kw0 + t4 + 4) * STRW + j0 + 8 + g];
#pragma unroll
            for (int nl = 0; nl < 8; nl++) {
                int n0 = 8 * (nh * 8 + nl);
                uint32_t bh[2], bl[2];
                bh[0] = W2h[(kw0 + t4) * STRW + n0 + g];
                bh[1] = W2h[(kw0 + t4 + 4) * STRW + n0 + g];
                bl[0] = W2l[(kw0 + t4) * STRW + n0 + g];
                bl[1] = W2l[(kw0 + t4 + 4) * STRW + n0 + g];
                mma_bf16(acc + 4 * nl, ah, bh);
                mma_bf16(acc + 4 * nl, ah, bl);
                mma_bf16(acc + 4 * nl, al, bh);
            }
        }

        // ---- Epilogue 2: pool (unimodal gelu -> only max/min of z) ----
#pragma unroll
        for (int nl = 0; nl < 8; nl++) {
            float mx0 = fmaxf(acc[4 * nl + 0], acc[4 * nl + 2]);
            float mn0 = fminf(acc[4 * nl + 0], acc[4 * nl + 2]);
            float mx1 = fmaxf(acc[4 * nl + 1], acc[4 * nl + 3]);
            float mn1 = fminf(acc[4 * nl + 1], acc[4 * nl + 3]);
#pragma unroll
            for (int off = 4; off < 32; off <<= 1) {
                mx0 = fmaxf(mx0, __shfl_xor_sync(0xffffffffu, mx0, off));
                mn0 = fminf(mn0, __shfl_xor_sync(0xffffffffu, mn0, off));
                mx1 = fmaxf(mx1, __shfl_xor_sync(0xffffffffu, mx1, off));
                mn1 = fminf(mn1, __shfl_xor_sync(0xffffffffu, mn1, off));
            }
            if (g == 0) {
                int c0 = 8 * (nh * 8 + nl) + 2 * t4;
                pool[(mw * 128 + c0) * 2 + 0] = mx0;
                pool[(mw * 128 + c0) * 2 + 1] = mn0;
                pool[(mw * 128 + c0 + 1) * 2 + 0] = mx1;
                pool[(mw * 128 + c0 + 1) * 2 + 1] = mn1;
            }
        }
        __syncthreads();

        {
            int grp = tid >> 7, col = tid & 127;
            int wA = grp * 2, wB = grp * 2 + 1;
            float mx = fmaxf(pool[(wA * 128 + col) * 2 + 0],
                             pool[(wB * 128 + col) * 2 + 0]);
            float mn = fminf(pool[(wA * 128 + col) * 2 + 1],
                             pool[(wB * 128 + col) * 2 + 1]);
            float bv = b2s[col];
            out_pooled[(size_t)(tile * 4 + grp) * Dx + col] =
                fmaxf(gelu_f(mx + bv), gelu_f(mn + bv));
        }
        __syncthreads();   // protect union region + pool before next gather
    }
}

// ---------------------------------------------------------------------------
extern "C" void kernel_launch(void* const* d_in, const int* in_sizes, int n_in,
                              void* d_out, int out_size) {
    (void)in_sizes; (void)n_in; (void)out_size;
    const float* coords   = (const float*)d_in[0];
    const float* features = (const float*)d_in[1];
    const float* W1 = (const float*)d_in[2];
    const float* b1 = (const float*)d_in[3];
    const float* W2 = (const float*)d_in[4];
    const float* b2 = (const float*)d_in[5];

    float* out = (float*)d_out;
    float* out_sampled = out;                       // (B,S,3)
    float* out_pooled  = out + (size_t)Bx * Sx * 3; // (B,S,128)

    cudaFuncSetAttribute(knn_part_kernel,
                         cudaFuncAttributeMaxDynamicSharedMemorySize,
                         HALF * (int)sizeof(float4));
    knn_part_kernel<<<1024, 512, HALF * sizeof(float4)>>>(coords);

    knn_merge_kernel<<<512, 512>>>(coords, out_sampled);

    cudaFuncSetAttribute(z1f_kernel,
                         cudaFuncAttributeMaxDynamicSharedMemorySize, SMEM_Z1F);
    z1f_kernel<<<Bx * Nx / 128, 256, SMEM_Z1F>>>(features, W1);

    cudaFuncSetAttribute(mlp_tc_kernel,
                         cudaFuncAttributeMaxDynamicSharedMemorySize, SMEM_MLP);
    mlp_tc_kernel<<<148, 512, SMEM_MLP>>>(
        coords, W1, b1, W2, b2, out_pooled);
}

// round 15
// speedup vs baseline: 1.0560x; 1.0560x over previous
#include <cuda_runtime.h>
#include <cuda_bf16.h>
#include <math.h>
#include <stdint.h>

#define Bx 4
#define Nx 8192
#define Cx 64
#define Dx 128
#define Sx 2048
#define Kx 32

// Scratch: packed points (x,y,z,|p|^2) and knn indices
__device__ float4 g_pts[Bx * Nx];
__device__ int g_knn[Bx * Sx * Kx];

// ---------------------------------------------------------------------------
// Math helpers
// ---------------------------------------------------------------------------
__device__ __forceinline__ float gelu_f(float x) {
    float z = fabsf(x) * 0.70710678118654752440f;
    float den = fmaf(0.3275911f, z, 1.0f);
    float t;
    asm("rcp.approx.f32 %0, %1;" : "=f"(t) : "f"(den));
    float poly = t * fmaf(t, fmaf(t, fmaf(t, fmaf(t, 1.061405429f, -1.453152027f),
                                          1.421413741f), -0.284496736f), 0.254829592f);
    float ex = __expf(-z * z);
    float e = fmaf(-poly, ex, 1.0f);
    float s = copysignf(e, x);
    return 0.5f * x * (1.0f + s);
}

__device__ __forceinline__ int sample_idx(int s) {
    float q = __fdiv_rn((float)s, 2047.0f);
    return __float2int_rn(__fmul_rn(8191.0f, q));
}

__device__ __forceinline__ unsigned ordf(float f) {
    unsigned u = __float_as_uint(f);
    return u ^ ((u >> 31) ? 0xffffffffu : 0x80000000u);
}

// bf16 hi/lo split of two floats -> packed hi-word and lo-word (x1 upper half)
__device__ __forceinline__ void split_pack2(float x0, float x1,
                                            uint32_t& hw, uint32_t& lw) {
    __nv_bfloat16 h0 = __float2bfloat16_rn(x0);
    __nv_bfloat16 h1 = __float2bfloat16_rn(x1);
    __nv_bfloat16 l0 = __float2bfloat16_rn(x0 - __bfloat162float(h0));
    __nv_bfloat16 l1 = __float2bfloat16_rn(x1 - __bfloat162float(h1));
    hw = ((uint32_t)__bfloat16_as_ushort(h1) << 16) | __bfloat16_as_ushort(h0);
    lw = ((uint32_t)__bfloat16_as_ushort(l1) << 16) | __bfloat16_as_ushort(l0);
}

// m16n8k16 bf16 mma, acc in-place
__device__ __forceinline__ void mma_bf16(float* c, const uint32_t* a,
                                         const uint32_t* b) {
    asm volatile(
        "mma.sync.aligned.m16n8k16.row.col.f32.bf16.bf16.f32 "
        "{%0,%1,%2,%3}, {%4,%5,%6,%7}, {%8,%9}, {%0,%1,%2,%3};"
        : "+f"(c[0]), "+f"(c[1]), "+f"(c[2]), "+f"(c[3])
        : "r"(a[0]), "r"(a[1]), "r"(a[2]), "r"(a[3]), "r"(b[0]), "r"(b[1]));
}

__device__ __forceinline__ void recompute_max(float held, int heldIdx,
                                              float& hmax, int& maxlane) {
    unsigned hk = ordf(held);
    unsigned mk = __reduce_max_sync(0xffffffffu, hk);
    unsigned mm = __ballot_sync(0xffffffffu, hk == mk);
    if (__popc(mm) > 1) {
        unsigned cand = (hk == mk) ? (unsigned)heldIdx : 0u;
        unsigned mi = __reduce_max_sync(0xffffffffu, cand);
        mm = __ballot_sync(0xffffffffu, (hk == mk) && ((unsigned)heldIdx == mi));
    }
    maxlane = __ffs(mm) - 1;
    hmax = __shfl_sync(0xffffffffu, held, maxlane);
}

// ---------------------------------------------------------------------------
// Kernel 1: pack points (x,y,z,|p|^2) + write sampled coords output
// ---------------------------------------------------------------------------
__global__ void prep_kernel(const float* __restrict__ coords,
                            float* __restrict__ out_sampled) {
    int t = blockIdx.x * blockDim.x + threadIdx.x;
    if (t < Bx * Nx) {
        float x = coords[3 * t + 0];
        float y = coords[3 * t + 1];
        float z = coords[3 * t + 2];
        g_pts[t] = make_float4(x, y, z, fmaf(z, z, fmaf(y, y, x * x)));
    }
    if (t < Bx * Sx) {
        int b = t / Sx;
        int s = t - b * Sx;
        int sidx = sample_idx(s);
        const float* c = coords + 3 * ((size_t)b * Nx + sidx);
        out_sampled[3 * t + 0] = c[0];
        out_sampled[3 * t + 1] = c[1];
        out_sampled[3 * t + 2] = c[2];
    }
}

// ---------------------------------------------------------------------------
// Kernel 2: full-scan kNN, LDG-based (no smem). One warp per query scans all
// 8192 candidates from L2-resident g_pts with 1-batch prefetch. Running
// top-32 distributed one (d2,idx) per lane; insert = replace warp lex-max.
// 512 thr/CTA, no smem -> up to 48+ warps/SM. Semantics identical to the
// half-split version (same seed, same eviction order, same fmaf d2).
// ---------------------------------------------------------------------------
__global__ __launch_bounds__(512, 3) void knn_full_kernel() {
    int wq = blockIdx.x * 16 + (threadIdx.x >> 5);   // 0..8191
    int b = wq >> 11;
    int s = wq & 2047;
    int lane = threadIdx.x & 31;
    const float4* __restrict__ pts = g_pts + (size_t)b * Nx;

    float4 sp = __ldg(&pts[sample_idx(s)]);
    float sx = sp.x, sy = sp.y, sz = sp.z, s2 = sp.w;

    // Seed: lane holds candidate `lane`
    float held;
    int heldIdx = lane;
    {
        float4 p = __ldg(&pts[lane]);
        held = fmaf(-2.0f, fmaf(sx, p.x, fmaf(sy, p.y, sz * p.z)), s2 + p.w);
    }
    float hmax;
    int maxlane;
    recompute_max(held, heldIdx, hmax, maxlane);

    // Main loop with one-batch prefetch
    float4 pn = __ldg(&pts[Kx + lane]);
    for (int n0 = Kx; n0 < Nx; n0 += 32) {
        float4 p = pn;
        if (n0 + 32 < Nx) pn = __ldg(&pts[n0 + 32 + lane]);
        float d = fmaf(-2.0f, fmaf(sx, p.x, fmaf(sy, p.y, sz * p.z)), s2 + p.w);
        unsigned qm = __ballot_sync(0xffffffffu, d < hmax);
        while (qm) {
            int src = __ffs(qm) - 1;
            qm &= qm - 1;
            float v = __shfl_sync(0xffffffffu, d, src);
            if (v < hmax) {          // re-check vs shrunken threshold
                if (lane == maxlane) { held = v; heldIdx = n0 + src; }
                recompute_max(held, heldIdx, hmax, maxlane);
            }
        }
    }

    g_knn[(size_t)wq * Kx + lane] = heldIdx;
}

// ---------------------------------------------------------------------------
// Kernel 3: MLP via mma.sync m16n8k16 bf16 (hi/lo 3-way split, pre-split
// packed operands) — r12 monolithic version (best measured).
// Persistent 148 CTAs x 256 thr. Tile = 4 groups = M128xN128.
//   Ah[64][136] Al[64][136]  (A1 uses kw 0..39, H uses 0..63)
//   W1h[40][136] W1l[40][136] W2h[64][136] W2l[64][136]
//   b1[128] b2[128] pool[8][128][2]
// ---------------------------------------------------------------------------
#define STRW 136
#define OFF_AH  0
#define OFF_AL  (64 * STRW)
#define OFF_W1H (OFF_AL + 64 * STRW)
#define OFF_W1L (OFF_W1H + 40 * STRW)
#define OFF_W2H (OFF_W1L + 40 * STRW)
#define OFF_W2L (OFF_W2H + 64 * STRW)
#define OFF_B1  (OFF_W2L + 64 * STRW)
#define OFF_B2  (OFF_B1 + 128)
#define OFF_PL  (OFF_B2 + 128)
#define SMEM_MLP ((OFF_PL + 8 * 128 * 2) * 4)  /* 192000 bytes */
#define NTILES (Bx * Sx / 4)

__global__ __launch_bounds__(256, 1) void mlp_tc_kernel(
    const float* __restrict__ coords,
    const float* __restrict__ features,
    const float* __restrict__ W1, const float* __restrict__ b1,
    const float* __restrict__ W2, const float* __restrict__ b2,
    float* __restrict__ out_pooled) {
    extern __shared__ uint32_t smu[];
    uint32_t* Ah  = smu + OFF_AH;
    uint32_t* Al  = smu + OFF_AL;
    uint32_t* W1h = smu + OFF_W1H;
    uint32_t* W1l = smu + OFF_W1L;
    uint32_t* W2h = smu + OFF_W2H;
    uint32_t* W2l = smu + OFF_W2L;
    float* b1s = (float*)(smu + OFF_B1);
    float* b2s = (float*)(smu + OFF_B2);
    float* pool = (float*)(smu + OFF_PL);

    int tid = threadIdx.x;
    int wm = tid >> 5, lane = tid & 31;
    int g = lane >> 2, t4 = lane & 3;
    int j0 = wm * 16;

    // Stage weights pre-split (once per CTA). Channel order c: 0-2 rel,
    // 3-66 features, 67-79 zero pad.
    for (int i = tid; i < 40 * 128; i += 256) {
        int kw = i >> 7, d = i & 127;
        int c0 = 2 * kw, c1 = 2 * kw + 1;
        float w0 = (c0 < 67) ? W1[c0 * Dx + d] : 0.0f;
        float w1 = (c1 < 67) ? W1[c1 * Dx + d] : 0.0f;
        uint32_t hw, lw;
        split_pack2(w0, w1, hw, lw);
        W1h[kw * STRW + d] = hw;
        W1l[kw * STRW + d] = lw;
    }
    for (int i = tid; i < 64 * 128; i += 256) {
        int kw = i >> 7, d = i & 127;
        float w0 = W2[(2 * kw) * Dx + d];
        float w1 = W2[(2 * kw + 1) * Dx + d];
        uint32_t hw, lw;
        split_pack2(w0, w1, hw, lw);
        W2h[kw * STRW + d] = hw;
        W2l[kw * STRW + d] = lw;
    }
    if (tid < 128) { b1s[tid] = b1[tid]; b2s[tid] = b2[tid]; }
    __syncthreads();

    for (int tile = blockIdx.x; tile < NTILES; tile += gridDim.x) {
        // ---- Gather A1 pre-split: row j = tid&127; hf=0 -> c 0..39,
        //      hf=1 -> c 40..79 (feats 37..63 + zero pad) ----
        {
            int j = tid & 127;
            int hf = tid >> 7;
            int group = tile * 4 + (j >> 5);
            int b = group >> 11, s = group & 2047;
            int ni = g_knn[(size_t)group * Kx + (j & 31)];
            const float4* f4 =
                (const float4*)(features + ((size_t)b * Nx + ni) * Cx);
            float va[40];
            if (hf == 0) {
                const float* sc = coords + 3 * ((size_t)b * Nx + sample_idx(s));
                const float* pc = coords + 3 * ((size_t)b * Nx + ni);
                va[0] = pc[0] - sc[0];
                va[1] = pc[1] - sc[1];
                va[2] = pc[2] - sc[2];
                float tf[40];
#pragma unroll
                for (int q = 0; q < 10; q++) {
                    float4 v = f4[q];
                    tf[4 * q] = v.x; tf[4 * q + 1] = v.y;
                    tf[4 * q + 2] = v.z; tf[4 * q + 3] = v.w;
                }
#pragma unroll
                for (int u = 0; u < 37; u++) va[3 + u] = tf[u];
            } else {
                float tf[28];
#pragma unroll
                for (int q = 0; q < 7; q++) {
                    float4 v = f4[9 + q];          // feats 36..63
                    tf[4 * q] = v.x; tf[4 * q + 1] = v.y;
                    tf[4 * q + 2] = v.z; tf[4 * q + 3] = v.w;
                }
#pragma unroll
                for (int u = 0; u < 27; u++) va[u] = tf[1 + u];  // feats 37..63
#pragma unroll
                for (int u = 27; u < 40; u++) va[u] = 0.0f;
            }
#pragma unroll
            for (int kw = 0; kw < 20; kw++) {
                uint32_t hw, lw;
                split_pack2(va[2 * kw], va[2 * kw + 1], hw, lw);
                int kwg = 20 * hf + kw;
                Ah[kwg * STRW + j] = hw;
                Al[kwg * STRW + j] = lw;
            }
        }
        __syncthreads();

        float acc[64];

        // ---- Layer 1: Z1 = A1 @ W1, K=80 (5 k16 iters, 3 MMAs each) ----
#pragma unroll
        for (int i = 0; i < 64; i++) acc[i] = 0.0f;
#pragma unroll
        for (int k = 0; k < 5; k++) {
            int kw0 = 8 * k;
            uint32_t ah[4], al[4];
            ah[0] = Ah[(kw0 + t4) * STRW + j0 + g];
            ah[1] = Ah[(kw0 + t4) * STRW + j0 + 8 + g];
            ah[2] = Ah[(kw0 + t4 + 4) * STRW + j0 + g];
            ah[3] = Ah[(kw0 + t4 + 4) * STRW + j0 + 8 + g];
            al[0] = Al[(kw0 + t4) * STRW + j0 + g];
            al[1] = Al[(kw0 + t4) * STRW + j0 + 8 + g];
            al[2] = Al[(kw0 + t4 + 4) * STRW + j0 + g];
            al[3] = Al[(kw0 + t4 + 4) * STRW + j0 + 8 + g];
#pragma unroll
            for (int n = 0; n < 16; n++) {
                int n0 = 8 * n;
                uint32_t bh[2], bl[2];
                bh[0] = W1h[(kw0 + t4) * STRW + n0 + g];
                bh[1] = W1h[(kw0 + t4 + 4) * STRW + n0 + g];
                bl[0] = W1l[(kw0 + t4) * STRW + n0 + g];
                bl[1] = W1l[(kw0 + t4 + 4) * STRW + n0 + g];
                mma_bf16(acc + 4 * n, ah, bh);
                mma_bf16(acc + 4 * n, ah, bl);
                mma_bf16(acc + 4 * n, al, bh);
            }
        }
        __syncthreads();   // all warps done reading A1 before H overwrite

        // ---- Epilogue 1: H = gelu(z + b1), re-split into Ah/Al (kw 0..63) ----
#pragma unroll
        for (int n = 0; n < 16; n++) {
            int c0 = 8 * n + 2 * t4;
            int kw = 4 * n + t4;
            float bv0 = b1s[c0], bv1 = b1s[c0 + 1];
            uint32_t hw, lw;
            split_pack2(gelu_f(acc[4 * n + 0] + bv0),
                        gelu_f(acc[4 * n + 1] + bv1), hw, lw);
            Ah[kw * STRW + j0 + g] = hw;
            Al[kw * STRW + j0 + g] = lw;
            split_pack2(gelu_f(acc[4 * n + 2] + bv0),
                        gelu_f(acc[4 * n + 3] + bv1), hw, lw);
            Ah[kw * STRW + j0 + 8 + g] = hw;
            Al[kw * STRW + j0 + 8 + g] = lw;
        }
        __syncthreads();

        // ---- Layer 2: Z2 = H @ W2, K=128 (8 k16 iters) ----
#pragma unroll
        for (int i = 0; i < 64; i++) acc[i] = 0.0f;
#pragma unroll
        for (int k = 0; k < 8; k++) {
            int kw0 = 8 * k;
            uint32_t ah[4], al[4];
            ah[0] = Ah[(kw0 + t4) * STRW + j0 + g];
            ah[1] = Ah[(kw0 + t4) * STRW + j0 + 8 + g];
            ah[2] = Ah[(kw0 + t4 + 4) * STRW + j0 + g];
            ah[3] = Ah[(kw0 + t4 + 4) * STRW + j0 + 8 + g];
            al[0] = Al[(kw0 + t4) * STRW + j0 + g];
            al[1] = Al[(kw0 + t4) * STRW + j0 + 8 + g];
            al[2] = Al[(kw0 + t4 + 4) * STRW + j0 + g];
            al[3] = Al[(kw0 + t4 + 4) * STRW + j0 + 8 + g];
#pragma unroll
            for (int n = 0; n < 16; n++) {
                int n0 = 8 * n;
                uint32_t bh[2], bl[2];
                bh[0] = W2h[(kw0 + t4) * STRW + n0 + g];
                bh[1] = W2h[(kw0 + t4 + 4) * STRW + n0 + g];
                bl[0] = W2l[(kw0 + t4) * STRW + n0 + g];
                bl[1] = W2l[(kw0 + t4 + 4) * STRW + n0 + g];
                mma_bf16(acc + 4 * n, ah, bh);
                mma_bf16(acc + 4 * n, ah, bl);
                mma_bf16(acc + 4 * n, al, bh);
            }
        }

        // ---- Epilogue 2: pool (unimodal gelu: only max/min of z needed) ----
#pragma unroll
        for (int n = 0; n < 16; n++) {
            float mx0 = fmaxf(acc[4 * n + 0], acc[4 * n + 2]);
            float mn0 = fminf(acc[4 * n + 0], acc[4 * n + 2]);
            float mx1 = fmaxf(acc[4 * n + 1], acc[4 * n + 3]);
            float mn1 = fminf(acc[4 * n + 1], acc[4 * n + 3]);
#pragma unroll
            for (int off = 4; off < 32; off <<= 1) {
                mx0 = fmaxf(mx0, __shfl_xor_sync(0xffffffffu, mx0, off));
                mn0 = fminf(mn0, __shfl_xor_sync(0xffffffffu, mn0, off));
                mx1 = fmaxf(mx1, __shfl_xor_sync(0xffffffffu, mx1, off));
                mn1 = fminf(mn1, __shfl_xor_sync(0xffffffffu, mn1, off));
            }
            if (g == 0) {
                int c0 = 8 * n + 2 * t4;
                pool[(wm * 128 + c0) * 2 + 0] = mx0;
                pool[(wm * 128 + c0) * 2 + 1] = mn0;
                pool[(wm * 128 + c0 + 1) * 2 + 0] = mx1;
                pool[(wm * 128 + c0 + 1) * 2 + 1] = mn1;
            }
        }
        __syncthreads();

#pragma unroll
        for (int it = 0; it < 2; it++) {
            int item = tid + it * 256;
            int grp = item >> 7, col = item & 127;
            int wA = grp * 2, wB = grp * 2 + 1;
            float mx = fmaxf(pool[(wA * 128 + col) * 2 + 0],
                             pool[(wB * 128 + col) * 2 + 0]);
            float mn = fminf(pool[(wA * 128 + col) * 2 + 1],
                             pool[(wB * 128 + col) * 2 + 1]);
            float bv = b2s[col];
            out_pooled[(size_t)(tile * 4 + grp) * Dx + col] =
                fmaxf(gelu_f(mx + bv), gelu_f(mn + bv));
        }
        __syncthreads();   // protect Ah/Al + pool before next tile
    }
}

// ---------------------------------------------------------------------------
extern "C" void kernel_launch(void* const* d_in, const int* in_sizes, int n_in,
                              void* d_out, int out_size) {
    (void)in_sizes; (void)n_in; (void)out_size;
    const float* coords   = (const float*)d_in[0];
    const float* features = (const float*)d_in[1];
    const float* W1 = (const float*)d_in[2];
    const float* b1 = (const float*)d_in[3];
    const float* W2 = (const float*)d_in[4];
    const float* b2 = (const float*)d_in[5];

    float* out = (float*)d_out;
    float* out_sampled = out;                       // (B,S,3)
    float* out_pooled  = out + (size_t)Bx * Sx * 3; // (B,S,128)

    prep_kernel<<<(Bx * Nx + 255) / 256, 256>>>(coords, out_sampled);

    knn_full_kernel<<<Bx * Sx / 16, 512>>>();

    cudaFuncSetAttribute(mlp_tc_kernel,
                         cudaFuncAttributeMaxDynamicSharedMemorySize, SMEM_MLP);
    mlp_tc_kernel<<<148, 256, SMEM_MLP>>>(
        coords, features, W1, b1, W2, b2, out_pooled);
}

// round 16
// speedup vs baseline: 1.2656x; 1.1985x over previous
#include <cuda_runtime.h>
#include <cuda_fp16.h>
#include <math.h>
#include <stdint.h>

#define Bx 4
#define Nx 8192
#define Cx 64
#define Dx 128
#define Sx 2048
#define Kx 32

// Scratch: packed points (x,y,z,|p|^2) and knn indices
__device__ float4 g_pts[Bx * Nx];
__device__ int g_knn[Bx * Sx * Kx];

// ---------------------------------------------------------------------------
// Math helpers
// ---------------------------------------------------------------------------
__device__ __forceinline__ float gelu_f(float x) {
    float z = fabsf(x) * 0.70710678118654752440f;
    float den = fmaf(0.3275911f, z, 1.0f);
    float t;
    asm("rcp.approx.f32 %0, %1;" : "=f"(t) : "f"(den));
    float poly = t * fmaf(t, fmaf(t, fmaf(t, fmaf(t, 1.061405429f, -1.453152027f),
                                          1.421413741f), -0.284496736f), 0.254829592f);
    float ex = __expf(-z * z);
    float e = fmaf(-poly, ex, 1.0f);
    float s = copysignf(e, x);
    return 0.5f * x * (1.0f + s);
}

__device__ __forceinline__ int sample_idx(int s) {
    float q = __fdiv_rn((float)s, 2047.0f);
    return __float2int_rn(__fmul_rn(8191.0f, q));
}

__device__ __forceinline__ unsigned ordf(float f) {
    unsigned u = __float_as_uint(f);
    return u ^ ((u >> 31) ? 0xffffffffu : 0x80000000u);
}

// Pack two floats as fp16 pair (x1 in upper half)
__device__ __forceinline__ uint32_t packh2(float x0, float x1) {
    __half2 h = __floats2half2_rn(x0, x1);
    return *(uint32_t*)&h;
}
// fp16 hi/lo split of two floats -> packed hi-word and lo-word
__device__ __forceinline__ void splith2(float x0, float x1,
                                        uint32_t& hw, uint32_t& lw) {
    __half h0 = __float2half_rn(x0);
    __half h1 = __float2half_rn(x1);
    float l0 = x0 - __half2float(h0);
    float l1 = x1 - __half2float(h1);
    __half2 hh = __halves2half2(h0, h1);
    hw = *(uint32_t*)&hh;
    lw = packh2(l0, l1);
}

// m16n8k16 f16 mma, fp32 acc in-place
__device__ __forceinline__ void mma_f16(float* c, const uint32_t* a,
                                        const uint32_t* b) {
    asm volatile(
        "mma.sync.aligned.m16n8k16.row.col.f32.f16.f16.f32 "
        "{%0,%1,%2,%3}, {%4,%5,%6,%7}, {%8,%9}, {%0,%1,%2,%3};"
        : "+f"(c[0]), "+f"(c[1]), "+f"(c[2]), "+f"(c[3])
        : "r"(a[0]), "r"(a[1]), "r"(a[2]), "r"(a[3]), "r"(b[0]), "r"(b[1]));
}

__device__ __forceinline__ void recompute_max(float held, int heldIdx,
                                              float& hmax, int& maxlane) {
    unsigned hk = ordf(held);
    unsigned mk = __reduce_max_sync(0xffffffffu, hk);
    unsigned mm = __ballot_sync(0xffffffffu, hk == mk);
    if (__popc(mm) > 1) {
        unsigned cand = (hk == mk) ? (unsigned)heldIdx : 0u;
        unsigned mi = __reduce_max_sync(0xffffffffu, cand);
        mm = __ballot_sync(0xffffffffu, (hk == mk) && ((unsigned)heldIdx == mi));
    }
    maxlane = __ffs(mm) - 1;
    hmax = __shfl_sync(0xffffffffu, held, maxlane);
}

// ---------------------------------------------------------------------------
// Kernel 1: pack points (x,y,z,|p|^2) + write sampled coords output
// ---------------------------------------------------------------------------
__global__ void prep_kernel(const float* __restrict__ coords,
                            float* __restrict__ out_sampled) {
    int t = blockIdx.x * blockDim.x + threadIdx.x;
    if (t < Bx * Nx) {
        float x = coords[3 * t + 0];
        float y = coords[3 * t + 1];
        float z = coords[3 * t + 2];
        g_pts[t] = make_float4(x, y, z, fmaf(z, z, fmaf(y, y, x * x)));
    }
    if (t < Bx * Sx) {
        int b = t / Sx;
        int s = t - b * Sx;
        int sidx = sample_idx(s);
        const float* c = coords + 3 * ((size_t)b * Nx + sidx);
        out_sampled[3 * t + 0] = c[0];
        out_sampled[3 * t + 1] = c[1];
        out_sampled[3 * t + 2] = c[2];
    }
}

// ---------------------------------------------------------------------------
// Kernel 2: full-scan kNN, whole-batch smem tile (128 KB). 1024 thr = 32
// warps = 32 queries per CTA; 256 CTAs. One warp per query, single-pass
// top-32 (one (d2,idx) per lane; insert = replace warp lex-max).
// Neighbor sets bit-identical to prior rounds (same d2 fmaf, same order).
// ---------------------------------------------------------------------------
__global__ __launch_bounds__(1024, 1) void knn_tile_kernel() {
    extern __shared__ float4 sh[];          // Nx float4 = 128 KB
    int b = blockIdx.x >> 6;                // 64 CTAs per batch
    int s = ((blockIdx.x & 63) << 5) + (threadIdx.x >> 5);
    int lane = threadIdx.x & 31;

    for (int i = threadIdx.x; i < Nx; i += 1024)
        sh[i] = g_pts[(size_t)b * Nx + i];
    __syncthreads();

    float4 sp = sh[sample_idx(s)];
    float sx = sp.x, sy = sp.y, sz = sp.z, s2 = sp.w;

    // Seed: lane holds candidate `lane`
    float held;
    int heldIdx = lane;
    {
        float4 p = sh[lane];
        held = fmaf(-2.0f, fmaf(sx, p.x, fmaf(sy, p.y, sz * p.z)), s2 + p.w);
    }
    float hmax;
    int maxlane;
    recompute_max(held, heldIdx, hmax, maxlane);

    for (int n0 = Kx; n0 < Nx; n0 += 32) {
        float4 p = sh[n0 + lane];
        float d = fmaf(-2.0f, fmaf(sx, p.x, fmaf(sy, p.y, sz * p.z)), s2 + p.w);
        unsigned qm = __ballot_sync(0xffffffffu, d < hmax);
        while (qm) {
            int src = __ffs(qm) - 1;
            qm &= qm - 1;
            float v = __shfl_sync(0xffffffffu, d, src);
            if (v < hmax) {          // re-check vs shrunken threshold
                if (lane == maxlane) { held = v; heldIdx = n0 + src; }
                recompute_max(held, heldIdx, hmax, maxlane);
            }
        }
    }

    g_knn[((size_t)b * Sx + s) * Kx + lane] = heldIdx;
}

// ---------------------------------------------------------------------------
// Kernel 3: MLP via mma.sync m16n8k16 f16. A rounded to fp16 (single), W as
// fp16 hi+lo 2-split: z = A_h*W_h + A_h*W_l  (dropped A_l*W ~ 2^-11 rel).
// Persistent 148 CTAs x 256 thr. Tile = 4 groups = M128xN128.
//   Ah[64][136]  (A1 uses kw 0..39, H uses 0..63)
//   W1h[40][136] W1l[40][136] W2h[64][136] W2l[64][136]
//   b1[128] b2[128] pool[8][128][2]
// ---------------------------------------------------------------------------
#define STRW 136
#define OFF_AH  0
#define OFF_W1H (64 * STRW)
#define OFF_W1L (OFF_W1H + 40 * STRW)
#define OFF_W2H (OFF_W1L + 40 * STRW)
#define OFF_W2L (OFF_W2H + 64 * STRW)
#define OFF_B1  (OFF_W2L + 64 * STRW)
#define OFF_B2  (OFF_B1 + 128)
#define OFF_PL  (OFF_B2 + 128)
#define SMEM_MLP ((OFF_PL + 8 * 128 * 2) * 4)   /* 157184 bytes */
#define NTILES (Bx * Sx / 4)

__global__ __launch_bounds__(256, 1) void mlp_tc_kernel(
    const float* __restrict__ coords,
    const float* __restrict__ features,
    const float* __restrict__ W1, const float* __restrict__ b1,
    const float* __restrict__ W2, const float* __restrict__ b2,
    float* __restrict__ out_pooled) {
    extern __shared__ uint32_t smu[];
    uint32_t* Ah  = smu + OFF_AH;
    uint32_t* W1h = smu + OFF_W1H;
    uint32_t* W1l = smu + OFF_W1L;
    uint32_t* W2h = smu + OFF_W2H;
    uint32_t* W2l = smu + OFF_W2L;
    float* b1s = (float*)(smu + OFF_B1);
    float* b2s = (float*)(smu + OFF_B2);
    float* pool = (float*)(smu + OFF_PL);

    int tid = threadIdx.x;
    int wm = tid >> 5, lane = tid & 31;
    int g = lane >> 2, t4 = lane & 3;
    int j0 = wm * 16;

    // Stage weights pre-split (once per CTA). Channel order c: 0-2 rel,
    // 3-66 features, 67-79 zero pad.
    for (int i = tid; i < 40 * 128; i += 256) {
        int kw = i >> 7, d = i & 127;
        int c0 = 2 * kw, c1 = 2 * kw + 1;
        float w0 = (c0 < 67) ? W1[c0 * Dx + d] : 0.0f;
        float w1 = (c1 < 67) ? W1[c1 * Dx + d] : 0.0f;
        uint32_t hw, lw;
        splith2(w0, w1, hw, lw);
        W1h[kw * STRW + d] = hw;
        W1l[kw * STRW + d] = lw;
    }
    for (int i = tid; i < 64 * 128; i += 256) {
        int kw = i >> 7, d = i & 127;
        float w0 = W2[(2 * kw) * Dx + d];
        float w1 = W2[(2 * kw + 1) * Dx + d];
        uint32_t hw, lw;
        splith2(w0, w1, hw, lw);
        W2h[kw * STRW + d] = hw;
        W2l[kw * STRW + d] = lw;
    }
    if (tid < 128) { b1s[tid] = b1[tid]; b2s[tid] = b2[tid]; }
    __syncthreads();

    for (int tile = blockIdx.x; tile < NTILES; tile += gridDim.x) {
        // ---- Gather A1 (fp16-rounded): row j = tid&127; hf=0 -> c 0..39,
        //      hf=1 -> c 40..79 (feats 37..63 + zero pad) ----
        {
            int j = tid & 127;
            int hf = tid >> 7;
            int group = tile * 4 + (j >> 5);
            int b = group >> 11, s = group & 2047;
            int ni = g_knn[(size_t)group * Kx + (j & 31)];
            const float4* f4 =
                (const float4*)(features + ((size_t)b * Nx + ni) * Cx);
            float va[40];
            if (hf == 0) {
                const float* sc = coords + 3 * ((size_t)b * Nx + sample_idx(s));
                const float* pc = coords + 3 * ((size_t)b * Nx + ni);
                va[0] = pc[0] - sc[0];
                va[1] = pc[1] - sc[1];
                va[2] = pc[2] - sc[2];
                float tf[40];
#pragma unroll
                for (int q = 0; q < 10; q++) {
                    float4 v = f4[q];
                    tf[4 * q] = v.x; tf[4 * q + 1] = v.y;
                    tf[4 * q + 2] = v.z; tf[4 * q + 3] = v.w;
                }
#pragma unroll
                for (int u = 0; u < 37; u++) va[3 + u] = tf[u];
            } else {
                float tf[28];
#pragma unroll
                for (int q = 0; q < 7; q++) {
                    float4 v = f4[9 + q];          // feats 36..63
                    tf[4 * q] = v.x; tf[4 * q + 1] = v.y;
                    tf[4 * q + 2] = v.z; tf[4 * q + 3] = v.w;
                }
#pragma unroll
                for (int u = 0; u < 27; u++) va[u] = tf[1 + u];  // feats 37..63
#pragma unroll
                for (int u = 27; u < 40; u++) va[u] = 0.0f;
            }
#pragma unroll
            for (int kw = 0; kw < 20; kw++) {
                int kwg = 20 * hf + kw;
                Ah[kwg * STRW + j] = packh2(va[2 * kw], va[2 * kw + 1]);
            }
        }
        __syncthreads();

        float acc[64];

        // ---- Layer 1: Z1 = A1 @ W1, K=80 (5 k16 iters, 2 MMAs each) ----
#pragma unroll
        for (int i = 0; i < 64; i++) acc[i] = 0.0f;
#pragma unroll
        for (int k = 0; k < 5; k++) {
            int kw0 = 8 * k;
            uint32_t ah[4];
            ah[0] = Ah[(kw0 + t4) * STRW + j0 + g];
            ah[1] = Ah[(kw0 + t4) * STRW + j0 + 8 + g];
            ah[2] = Ah[(kw0 + t4 + 4) * STRW + j0 + g];
            ah[3] = Ah[(kw0 + t4 + 4) * STRW + j0 + 8 + g];
#pragma unroll
            for (int n = 0; n < 16; n++) {
                int n0 = 8 * n;
                uint32_t bh[2], bl[2];
                bh[0] = W1h[(kw0 + t4) * STRW + n0 + g];
                bh[1] = W1h[(kw0 + t4 + 4) * STRW + n0 + g];
                bl[0] = W1l[(kw0 + t4) * STRW + n0 + g];
                bl[1] = W1l[(kw0 + t4 + 4) * STRW + n0 + g];
                mma_f16(acc + 4 * n, ah, bh);
                mma_f16(acc + 4 * n, ah, bl);
            }
        }
        __syncthreads();   // all warps done reading A1 before H overwrite

        // ---- Epilogue 1: H = gelu(z + b1), fp16-round into Ah (kw 0..63) ----
#pragma unroll
        for (int n = 0; n < 16; n++) {
            int c0 = 8 * n + 2 * t4;
            int kw = 4 * n + t4;
            float bv0 = b1s[c0], bv1 = b1s[c0 + 1];
            Ah[kw * STRW + j0 + g] =
                packh2(gelu_f(acc[4 * n + 0] + bv0), gelu_f(acc[4 * n + 1] + bv1));
            Ah[kw * STRW + j0 + 8 + g] =
                packh2(gelu_f(acc[4 * n + 2] + bv0), gelu_f(acc[4 * n + 3] + bv1));
        }
        __syncthreads();

        // ---- Layer 2: Z2 = H @ W2, K=128 (8 k16 iters) ----
#pragma unroll
        for (int i = 0; i < 64; i++) acc[i] = 0.0f;
#pragma unroll
        for (int k = 0; k < 8; k++) {
            int kw0 = 8 * k;
            uint32_t ah[4];
            ah[0] = Ah[(kw0 + t4) * STRW + j0 + g];
            ah[1] = Ah[(kw0 + t4) * STRW + j0 + 8 + g];
            ah[2] = Ah[(kw0 + t4 + 4) * STRW + j0 + g];
            ah[3] = Ah[(kw0 + t4 + 4) * STRW + j0 + 8 + g];
#pragma unroll
            for (int n = 0; n < 16; n++) {
                int n0 = 8 * n;
                uint32_t bh[2], bl[2];
                bh[0] = W2h[(kw0 + t4) * STRW + n0 + g];
                bh[1] = W2h[(kw0 + t4 + 4) * STRW + n0 + g];
                bl[0] = W2l[(kw0 + t4) * STRW + n0 + g];
                bl[1] = W2l[(kw0 + t4 + 4) * STRW + n0 + g];
                mma_f16(acc + 4 * n, ah, bh);
                mma_f16(acc + 4 * n, ah, bl);
            }
        }

        // ---- Epilogue 2: pool (unimodal gelu: only max/min of z needed) ----
#pragma unroll
        for (int n = 0; n < 16; n++) {
            float mx0 = fmaxf(acc[4 * n + 0], acc[4 * n + 2]);
            float mn0 = fminf(acc[4 * n + 0], acc[4 * n + 2]);
            float mx1 = fmaxf(acc[4 * n + 1], acc[4 * n + 3]);
            float mn1 = fminf(acc[4 * n + 1], acc[4 * n + 3]);
#pragma unroll
            for (int off = 4; off < 32; off <<= 1) {
                mx0 = fmaxf(mx0, __shfl_xor_sync(0xffffffffu, mx0, off));
                mn0 = fminf(mn0, __shfl_xor_sync(0xffffffffu, mn0, off));
                mx1 = fmaxf(mx1, __shfl_xor_sync(0xffffffffu, mx1, off));
                mn1 = fminf(mn1, __shfl_xor_sync(0xffffffffu, mn1, off));
            }
            if (g == 0) {
                int c0 = 8 * n + 2 * t4;
                pool[(wm * 128 + c0) * 2 + 0] = mx0;
                pool[(wm * 128 + c0) * 2 + 1] = mn0;
                pool[(wm * 128 + c0 + 1) * 2 + 0] = mx1;
                pool[(wm * 128 + c0 + 1) * 2 + 1] = mn1;
            }
        }
        __syncthreads();

#pragma unroll
        for (int it = 0; it < 2; it++) {
            int item = tid + it * 256;
            int grp = item >> 7, col = item & 127;
            int wA = grp * 2, wB = grp * 2 + 1;
            float mx = fmaxf(pool[(wA * 128 + col) * 2 + 0],
                             pool[(wB * 128 + col) * 2 + 0]);
            float mn = fminf(pool[(wA * 128 + col) * 2 + 1],
                             pool[(wB * 128 + col) * 2 + 1]);
            float bv = b2s[col];
            out_pooled[(size_t)(tile * 4 + grp) * Dx + col] =
                fmaxf(gelu_f(mx + bv), gelu_f(mn + bv));
        }
        __syncthreads();   // protect Ah + pool before next tile
    }
}

// ---------------------------------------------------------------------------
extern "C" void kernel_launch(void* const* d_in, const int* in_sizes, int n_in,
                              void* d_out, int out_size) {
    (void)in_sizes; (void)n_in; (void)out_size;
    const float* coords   = (const float*)d_in[0];
    const float* features = (const float*)d_in[1];
    const float* W1 = (const float*)d_in[2];
    const float* b1 = (const float*)d_in[3];
    const float* W2 = (const float*)d_in[4];
    const float* b2 = (const float*)d_in[5];

    float* out = (float*)d_out;
    float* out_sampled = out;                       // (B,S,3)
    float* out_pooled  = out + (size_t)Bx * Sx * 3; // (B,S,128)

    prep_kernel<<<(Bx * Nx + 255) / 256, 256>>>(coords, out_sampled);

    cudaFuncSetAttribute(knn_tile_kernel,
                         cudaFuncAttributeMaxDynamicSharedMemorySize,
                         Nx * (int)sizeof(float4));
    knn_tile_kernel<<<Bx * 64, 1024, Nx * sizeof(float4)>>>();

    cudaFuncSetAttribute(mlp_tc_kernel,
                         cudaFuncAttributeMaxDynamicSharedMemorySize, SMEM_MLP);
    mlp_tc_kernel<<<148, 256, SMEM_MLP>>>(
        coords, features, W1, b1, W2, b2, out_pooled);
}

// round 17
// speedup vs baseline: 1.4796x; 1.1691x over previous
#include <cuda_runtime.h>
#include <cuda_fp16.h>
#include <math.h>
#include <stdint.h>

#define Bx 4
#define Nx 8192
#define Cx 64
#define Dx 128
#define Sx 2048
#define Kx 32

// Scratch: packed points (x,y,z,|p|^2) and knn indices
__device__ float4 g_pts[Bx * Nx];
__device__ int g_knn[Bx * Sx * Kx];

// ---------------------------------------------------------------------------
// Math helpers
// ---------------------------------------------------------------------------
__device__ __forceinline__ float gelu_f(float x) {
    float z = fabsf(x) * 0.70710678118654752440f;
    float den = fmaf(0.3275911f, z, 1.0f);
    float t;
    asm("rcp.approx.f32 %0, %1;" : "=f"(t) : "f"(den));
    float poly = t * fmaf(t, fmaf(t, fmaf(t, fmaf(t, 1.061405429f, -1.453152027f),
                                          1.421413741f), -0.284496736f), 0.254829592f);
    float ex = __expf(-z * z);
    float e = fmaf(-poly, ex, 1.0f);
    float s = copysignf(e, x);
    return 0.5f * x * (1.0f + s);
}

__device__ __forceinline__ int sample_idx(int s) {
    float q = __fdiv_rn((float)s, 2047.0f);
    return __float2int_rn(__fmul_rn(8191.0f, q));
}

__device__ __forceinline__ unsigned ordf(float f) {
    unsigned u = __float_as_uint(f);
    return u ^ ((u >> 31) ? 0xffffffffu : 0x80000000u);
}

// Pack two floats as fp16 pair (x1 in upper half)
__device__ __forceinline__ uint32_t packh2(float x0, float x1) {
    __half2 h = __floats2half2_rn(x0, x1);
    return *(uint32_t*)&h;
}

// m16n8k16 f16 mma, fp32 acc in-place
__device__ __forceinline__ void mma_f16(float* c, const uint32_t* a,
                                        const uint32_t* b) {
    asm volatile(
        "mma.sync.aligned.m16n8k16.row.col.f32.f16.f16.f32 "
        "{%0,%1,%2,%3}, {%4,%5,%6,%7}, {%8,%9}, {%0,%1,%2,%3};"
        : "+f"(c[0]), "+f"(c[1]), "+f"(c[2]), "+f"(c[3])
        : "r"(a[0]), "r"(a[1]), "r"(a[2]), "r"(a[3]), "r"(b[0]), "r"(b[1]));
}

__device__ __forceinline__ void recompute_max(float held, int heldIdx,
                                              float& hmax, int& maxlane) {
    unsigned hk = ordf(held);
    unsigned mk = __reduce_max_sync(0xffffffffu, hk);
    unsigned mm = __ballot_sync(0xffffffffu, hk == mk);
    if (__popc(mm) > 1) {
        unsigned cand = (hk == mk) ? (unsigned)heldIdx : 0u;
        unsigned mi = __reduce_max_sync(0xffffffffu, cand);
        mm = __ballot_sync(0xffffffffu, (hk == mk) && ((unsigned)heldIdx == mi));
    }
    maxlane = __ffs(mm) - 1;
    hmax = __shfl_sync(0xffffffffu, held, maxlane);
}

// ---------------------------------------------------------------------------
// Kernel 1: pack points (x,y,z,|p|^2) + write sampled coords output
// ---------------------------------------------------------------------------
__global__ void prep_kernel(const float* __restrict__ coords,
                            float* __restrict__ out_sampled) {
    int t = blockIdx.x * blockDim.x + threadIdx.x;
    if (t < Bx * Nx) {
        float x = coords[3 * t + 0];
        float y = coords[3 * t + 1];
        float z = coords[3 * t + 2];
        g_pts[t] = make_float4(x, y, z, fmaf(z, z, fmaf(y, y, x * x)));
    }
    if (t < Bx * Sx) {
        int b = t / Sx;
        int s = t - b * Sx;
        int sidx = sample_idx(s);
        const float* c = coords + 3 * ((size_t)b * Nx + sidx);
        out_sampled[3 * t + 0] = c[0];
        out_sampled[3 * t + 1] = c[1];
        out_sampled[3 * t + 2] = c[2];
    }
}

// ---------------------------------------------------------------------------
// Kernel 2: full-scan kNN, whole-batch smem tile (128 KB). 1024 thr = 32
// warps = 32 queries per CTA; 256 CTAs. One warp per query, single-pass
// top-32 (one (d2,idx) per lane; insert = replace warp lex-max).
// ---------------------------------------------------------------------------
__global__ __launch_bounds__(1024, 1) void knn_tile_kernel() {
    extern __shared__ float4 sh[];          // Nx float4 = 128 KB
    int b = blockIdx.x >> 6;                // 64 CTAs per batch
    int s = ((blockIdx.x & 63) << 5) + (threadIdx.x >> 5);
    int lane = threadIdx.x & 31;

    for (int i = threadIdx.x; i < Nx; i += 1024)
        sh[i] = g_pts[(size_t)b * Nx + i];
    __syncthreads();

    float4 sp = sh[sample_idx(s)];
    float sx = sp.x, sy = sp.y, sz = sp.z, s2 = sp.w;

    float held;
    int heldIdx = lane;
    {
        float4 p = sh[lane];
        held = fmaf(-2.0f, fmaf(sx, p.x, fmaf(sy, p.y, sz * p.z)), s2 + p.w);
    }
    float hmax;
    int maxlane;
    recompute_max(held, heldIdx, hmax, maxlane);

    for (int n0 = Kx; n0 < Nx; n0 += 32) {
        float4 p = sh[n0 + lane];
        float d = fmaf(-2.0f, fmaf(sx, p.x, fmaf(sy, p.y, sz * p.z)), s2 + p.w);
        unsigned qm = __ballot_sync(0xffffffffu, d < hmax);
        while (qm) {
            int src = __ffs(qm) - 1;
            qm &= qm - 1;
            float v = __shfl_sync(0xffffffffu, d, src);
            if (v < hmax) {          // re-check vs shrunken threshold
                if (lane == maxlane) { held = v; heldIdx = n0 + src; }
                recompute_max(held, heldIdx, hmax, maxlane);
            }
        }
    }

    g_knn[((size_t)b * Sx + s) * Kx + lane] = heldIdx;
}

// ---------------------------------------------------------------------------
// Kernel 3: MLP via mma.sync m16n8k16 f16, SINGLE fp16 operands (A and W).
// 1 MMA per (k,n). smem ~100.6 KB -> 2 CTAs/SM. Persistent 296 CTAs x 256 thr.
//   Ah[64][136]  (A1 uses kw 0..39, H uses 0..63)
//   W1h[40][136] W2h[64][136]  b1[128] b2[128] pool[8][128][2]
// ---------------------------------------------------------------------------
#define STRW 136
#define OFF_AH  0
#define OFF_W1H (64 * STRW)
#define OFF_W2H (OFF_W1H + 40 * STRW)
#define OFF_B1  (OFF_W2H + 64 * STRW)
#define OFF_B2  (OFF_B1 + 128)
#define OFF_PL  (OFF_B2 + 128)
#define SMEM_MLP ((OFF_PL + 8 * 128 * 2) * 4)   /* 100608 bytes */
#define NTILES (Bx * Sx / 4)

__global__ __launch_bounds__(256, 2) void mlp_tc_kernel(
    const float* __restrict__ coords,
    const float* __restrict__ features,
    const float* __restrict__ W1, const float* __restrict__ b1,
    const float* __restrict__ W2, const float* __restrict__ b2,
    float* __restrict__ out_pooled) {
    extern __shared__ uint32_t smu[];
    uint32_t* Ah  = smu + OFF_AH;
    uint32_t* W1h = smu + OFF_W1H;
    uint32_t* W2h = smu + OFF_W2H;
    float* b1s = (float*)(smu + OFF_B1);
    float* b2s = (float*)(smu + OFF_B2);
    float* pool = (float*)(smu + OFF_PL);

    int tid = threadIdx.x;
    int wm = tid >> 5, lane = tid & 31;
    int g = lane >> 2, t4 = lane & 3;
    int j0 = wm * 16;

    // Stage weights fp16-rounded (once per CTA). Channel order c: 0-2 rel,
    // 3-66 features, 67-79 zero pad.
    for (int i = tid; i < 40 * 128; i += 256) {
        int kw = i >> 7, d = i & 127;
        int c0 = 2 * kw, c1 = 2 * kw + 1;
        float w0 = (c0 < 67) ? W1[c0 * Dx + d] : 0.0f;
        float w1 = (c1 < 67) ? W1[c1 * Dx + d] : 0.0f;
        W1h[kw * STRW + d] = packh2(w0, w1);
    }
    for (int i = tid; i < 64 * 128; i += 256) {
        int kw = i >> 7, d = i & 127;
        W2h[kw * STRW + d] =
            packh2(W2[(2 * kw) * Dx + d], W2[(2 * kw + 1) * Dx + d]);
    }
    if (tid < 128) { b1s[tid] = b1[tid]; b2s[tid] = b2[tid]; }
    __syncthreads();

    for (int tile = blockIdx.x; tile < NTILES; tile += gridDim.x) {
        // ---- Gather A1 (fp16-rounded): row j = tid&127; hf=0 -> c 0..39,
        //      hf=1 -> c 40..79 (feats 37..63 + zero pad) ----
        {
            int j = tid & 127;
            int hf = tid >> 7;
            int group = tile * 4 + (j >> 5);
            int b = group >> 11, s = group & 2047;
            int ni = g_knn[(size_t)group * Kx + (j & 31)];
            const float4* f4 =
                (const float4*)(features + ((size_t)b * Nx + ni) * Cx);
            float va[40];
            if (hf == 0) {
                const float* sc = coords + 3 * ((size_t)b * Nx + sample_idx(s));
                const float* pc = coords + 3 * ((size_t)b * Nx + ni);
                va[0] = pc[0] - sc[0];
                va[1] = pc[1] - sc[1];
                va[2] = pc[2] - sc[2];
                float tf[40];
#pragma unroll
                for (int q = 0; q < 10; q++) {
                    float4 v = f4[q];
                    tf[4 * q] = v.x; tf[4 * q + 1] = v.y;
                    tf[4 * q + 2] = v.z; tf[4 * q + 3] = v.w;
                }
#pragma unroll
                for (int u = 0; u < 37; u++) va[3 + u] = tf[u];
            } else {
                float tf[28];
#pragma unroll
                for (int q = 0; q < 7; q++) {
                    float4 v = f4[9 + q];          // feats 36..63
                    tf[4 * q] = v.x; tf[4 * q + 1] = v.y;
                    tf[4 * q + 2] = v.z; tf[4 * q + 3] = v.w;
                }
#pragma unroll
                for (int u = 0; u < 27; u++) va[u] = tf[1 + u];  // feats 37..63
#pragma unroll
                for (int u = 27; u < 40; u++) va[u] = 0.0f;
            }
#pragma unroll
            for (int kw = 0; kw < 20; kw++) {
                int kwg = 20 * hf + kw;
                Ah[kwg * STRW + j] = packh2(va[2 * kw], va[2 * kw + 1]);
            }
        }
        __syncthreads();

        float acc[64];

        // ---- Layer 1: Z1 = A1 @ W1, K=80 (5 k16 iters, 1 MMA each) ----
#pragma unroll
        for (int i = 0; i < 64; i++) acc[i] = 0.0f;
#pragma unroll
        for (int k = 0; k < 5; k++) {
            int kw0 = 8 * k;
            uint32_t ah[4];
            ah[0] = Ah[(kw0 + t4) * STRW + j0 + g];
            ah[1] = Ah[(kw0 + t4) * STRW + j0 + 8 + g];
            ah[2] = Ah[(kw0 + t4 + 4) * STRW + j0 + g];
            ah[3] = Ah[(kw0 + t4 + 4) * STRW + j0 + 8 + g];
#pragma unroll
            for (int n = 0; n < 16; n++) {
                int n0 = 8 * n;
                uint32_t bh[2];
                bh[0] = W1h[(kw0 + t4) * STRW + n0 + g];
                bh[1] = W1h[(kw0 + t4 + 4) * STRW + n0 + g];
                mma_f16(acc + 4 * n, ah, bh);
            }
        }
        __syncthreads();   // all warps done reading A1 before H overwrite

        // ---- Epilogue 1: H = gelu(z + b1), fp16-round into Ah (kw 0..63) ----
#pragma unroll
        for (int n = 0; n < 16; n++) {
            int c0 = 8 * n + 2 * t4;
            int kw = 4 * n + t4;
            float bv0 = b1s[c0], bv1 = b1s[c0 + 1];
            Ah[kw * STRW + j0 + g] =
                packh2(gelu_f(acc[4 * n + 0] + bv0), gelu_f(acc[4 * n + 1] + bv1));
            Ah[kw * STRW + j0 + 8 + g] =
                packh2(gelu_f(acc[4 * n + 2] + bv0), gelu_f(acc[4 * n + 3] + bv1));
        }
        __syncthreads();

        // ---- Layer 2: Z2 = H @ W2, K=128 (8 k16 iters, 1 MMA each) ----
#pragma unroll
        for (int i = 0; i < 64; i++) acc[i] = 0.0f;
#pragma unroll
        for (int k = 0; k < 8; k++) {
            int kw0 = 8 * k;
            uint32_t ah[4];
            ah[0] = Ah[(kw0 + t4) * STRW + j0 + g];
            ah[1] = Ah[(kw0 + t4) * STRW + j0 + 8 + g];
            ah[2] = Ah[(kw0 + t4 + 4) * STRW + j0 + g];
            ah[3] = Ah[(kw0 + t4 + 4) * STRW + j0 + 8 + g];
#pragma unroll
            for (int n = 0; n < 16; n++) {
                int n0 = 8 * n;
                uint32_t bh[2];
                bh[0] = W2h[(kw0 + t4) * STRW + n0 + g];
                bh[1] = W2h[(kw0 + t4 + 4) * STRW + n0 + g];
                mma_f16(acc + 4 * n, ah, bh);
            }
        }

        // ---- Epilogue 2: pool (unimodal gelu: only max/min of z needed) ----
#pragma unroll
        for (int n = 0; n < 16; n++) {
            float mx0 = fmaxf(acc[4 * n + 0], acc[4 * n + 2]);
            float mn0 = fminf(acc[4 * n + 0], acc[4 * n + 2]);
            float mx1 = fmaxf(acc[4 * n + 1], acc[4 * n + 3]);
            float mn1 = fminf(acc[4 * n + 1], acc[4 * n + 3]);
#pragma unroll
            for (int off = 4; off < 32; off <<= 1) {
                mx0 = fmaxf(mx0, __shfl_xor_sync(0xffffffffu, mx0, off));
                mn0 = fminf(mn0, __shfl_xor_sync(0xffffffffu, mn0, off));
                mx1 = fmaxf(mx1, __shfl_xor_sync(0xffffffffu, mx1, off));
                mn1 = fminf(mn1, __shfl_xor_sync(0xffffffffu, mn1, off));
            }
            if (g == 0) {
                int c0 = 8 * n + 2 * t4;
                pool[(wm * 128 + c0) * 2 + 0] = mx0;
                pool[(wm * 128 + c0) * 2 + 1] = mn0;
                pool[(wm * 128 + c0 + 1) * 2 + 0] = mx1;
                pool[(wm * 128 + c0 + 1) * 2 + 1] = mn1;
            }
        }
        __syncthreads();

#pragma unroll
        for (int it = 0; it < 2; it++) {
            int item = tid + it * 256;
            int grp = item >> 7, col = item & 127;
            int wA = grp * 2, wB = grp * 2 + 1;
            float mx = fmaxf(pool[(wA * 128 + col) * 2 + 0],
                             pool[(wB * 128 + col) * 2 + 0]);
            float mn = fminf(pool[(wA * 128 + col) * 2 + 1],
                             pool[(wB * 128 + col) * 2 + 1]);
            float bv = b2s[col];
            out_pooled[(size_t)(tile * 4 + grp) * Dx + col] =
                fmaxf(gelu_f(mx + bv), gelu_f(mn + bv));
        }
        __syncthreads();   // protect Ah + pool before next tile
    }
}

// ---------------------------------------------------------------------------
extern "C" void kernel_launch(void* const* d_in, const int* in_sizes, int n_in,
                              void* d_out, int out_size) {
    (void)in_sizes; (void)n_in; (void)out_size;
    const float* coords   = (const float*)d_in[0];
    const float* features = (const float*)d_in[1];
    const float* W1 = (const float*)d_in[2];
    const float* b1 = (const float*)d_in[3];
    const float* W2 = (const float*)d_in[4];
    const float* b2 = (const float*)d_in[5];

    float* out = (float*)d_out;
    float* out_sampled = out;                       // (B,S,3)
    float* out_pooled  = out + (size_t)Bx * Sx * 3; // (B,S,128)

    prep_kernel<<<(Bx * Nx + 255) / 256, 256>>>(coords, out_sampled);

    cudaFuncSetAttribute(knn_tile_kernel,
                         cudaFuncAttributeMaxDynamicSharedMemorySize,
                         Nx * (int)sizeof(float4));
    knn_tile_kernel<<<Bx * 64, 1024, Nx * sizeof(float4)>>>();

    cudaFuncSetAttribute(mlp_tc_kernel,
                         cudaFuncAttributeMaxDynamicSharedMemorySize, SMEM_MLP);
    mlp_tc_kernel<<<296, 256, SMEM_MLP>>>(
        coords, features, W1, b1, W2, b2, out_pooled);
}